// round 5
// baseline (speedup 1.0000x reference)
#include <cuda_runtime.h>
#include <cuda_fp16.h>
#include <cstdint>

#define B_      1024
#define N_      4096
#define L_      8
#define K_      16
#define G_      8            // batch rows per block
#define THREADS_ 1024
#define NBLOCKS_ (B_ / G_)   // 128

// Scratch: schedule-permuted indices (uint16) and weights (fp32).
__device__ __align__(16) uint16_t g_src16[L_ * N_ * K_];   // 1 MB
__device__ __align__(16) float    g_wperm[L_ * N_ * K_];   // 2 MB

// Joint per-octet gather scheduler.
// In the main kernel, lanes 0-7 / 8-15 / ... of a warp form the LDS.128
// crossbar phases, and lane l of an octet processes n = octet_base + l.
// Each lane has 16 commutable (s, w) pairs; a bank conflict occurs when two
// lanes of the same phase read different addresses in the same bank-group
// (s & 7) at the same k-step. One prep thread schedules a whole octet:
// for each of 16 steps, each lane greedily picks an unscheduled pair whose
// bank-group is not yet claimed in this step (lane order rotates with the
// step so no lane is systematically last). Near-Latin-square schedule =>
// conflict replay factor ~1.1-1.3 instead of ~2.4 for random order.
__global__ void prep_sched(const int* __restrict__ src,
                           const float* __restrict__ w) {
    int t = blockIdx.x * blockDim.x + threadIdx.x;   // octet id
    if (t >= L_ * (N_ / 8)) return;
    int l  = t / (N_ / 8);
    int n0 = (t % (N_ / 8)) * 8;

    uint16_t s[8][K_];
    float    wv[8][K_];
    #pragma unroll
    for (int lane = 0; lane < 8; lane++) {
        const int*   sp = src + ((size_t)l * N_ + n0 + lane) * K_;
        const float* wp = w   + ((size_t)l * N_ + n0 + lane) * K_;
        #pragma unroll
        for (int k = 0; k < K_; k++) {
            s[lane][k]  = (uint16_t)sp[k];
            wv[lane][k] = wp[k];
        }
    }

    unsigned rem[8];
    #pragma unroll
    for (int lane = 0; lane < 8; lane++) rem[lane] = 0xFFFFu;

    for (int step = 0; step < K_; step++) {
        unsigned groupmask = 0;
        #pragma unroll 1
        for (int li = 0; li < 8; li++) {
            int lane = (li + step) & 7;           // rotate start lane
            int pick = -1, fallback = -1;
            #pragma unroll 1
            for (int k = 0; k < K_; k++) {
                if (!((rem[lane] >> k) & 1u)) continue;
                if (fallback < 0) fallback = k;
                int g = s[lane][k] & 7;
                if (!((groupmask >> g) & 1u)) { pick = k; break; }
            }
            if (pick < 0) pick = fallback;        // forced collision
            rem[lane] &= ~(1u << pick);
            groupmask |= 1u << (s[lane][pick] & 7);

            size_t base = ((size_t)l * N_ + n0 + lane) * K_ + step;
            g_src16[base] = s[lane][pick];
            g_wperm[base] = wv[lane][pick];
        }
    }
}

// One gather index serves all G=8 batch rows: one LDS.128 of [s][0..7] fp16.
__device__ __forceinline__ void gather_fma(const __half* __restrict__ cur,
                                           uint32_t s, float wk, float* acc) {
    uint4 v = *reinterpret_cast<const uint4*>(cur + s * G_);
    float2 f;
    f = __half22float2(*reinterpret_cast<__half2*>(&v.x));
    acc[0] = fmaf(f.x, wk, acc[0]); acc[1] = fmaf(f.y, wk, acc[1]);
    f = __half22float2(*reinterpret_cast<__half2*>(&v.y));
    acc[2] = fmaf(f.x, wk, acc[2]); acc[3] = fmaf(f.y, wk, acc[3]);
    f = __half22float2(*reinterpret_cast<__half2*>(&v.z));
    acc[4] = fmaf(f.x, wk, acc[4]); acc[5] = fmaf(f.y, wk, acc[5]);
    f = __half22float2(*reinterpret_cast<__half2*>(&v.w));
    acc[6] = fmaf(f.x, wk, acc[6]); acc[7] = fmaf(f.y, wk, acc[7]);
}

__device__ __forceinline__ void half_k(const __half* __restrict__ cur,
                                       uint4 s, const float4* __restrict__ wv,
                                       float* acc) {
    float4 wa = wv[0];
    gather_fma(cur, s.x & 0xFFFFu, wa.x, acc);
    gather_fma(cur, s.x >> 16,     wa.y, acc);
    gather_fma(cur, s.y & 0xFFFFu, wa.z, acc);
    gather_fma(cur, s.y >> 16,     wa.w, acc);
    float4 wb = wv[1];
    gather_fma(cur, s.z & 0xFFFFu, wb.x, acc);
    gather_fma(cur, s.z >> 16,     wb.y, acc);
    gather_fma(cur, s.w & 0xFFFFu, wb.z, acc);
    gather_fma(cur, s.w >> 16,     wb.w, acc);
}

__global__ void __launch_bounds__(THREADS_, 1)
genome_kernel(const float* __restrict__ x, float* __restrict__ out) {
    extern __shared__ __half sm[];
    __half* bufA = sm;               // [N_][G_]
    __half* bufB = sm + N_ * G_;     // double buffer
    const int b0 = blockIdx.x * G_;

    for (int n = threadIdx.x; n < N_; n += THREADS_) {
        __half tmp[G_];
        #pragma unroll
        for (int g = 0; g < G_; g++)
            tmp[g] = __float2half_rn(x[(size_t)(b0 + g) * N_ + n]);
        *reinterpret_cast<uint4*>(bufA + (size_t)n * G_) =
            *reinterpret_cast<uint4*>(tmp);
    }
    __syncthreads();

    #pragma unroll 1
    for (int l = 0; l < L_; l++) {
        const __half* cur = (l & 1) ? bufB : bufA;
        __half*       nxt = (l & 1) ? bufA : bufB;
        const uint4*  srcv = reinterpret_cast<const uint4*>(g_src16) + (size_t)l * N_ * 2;
        const float4* wv   = reinterpret_cast<const float4*>(g_wperm) + (size_t)l * N_ * 4;
        const bool last = (l == L_ - 1);

        #pragma unroll 1
        for (int n = threadIdx.x; n < N_; n += THREADS_) {
            float acc[G_];
            #pragma unroll
            for (int g = 0; g < G_; g++) acc[g] = 0.0f;

            half_k(cur, srcv[n * 2 + 0], wv + n * 4 + 0, acc);
            half_k(cur, srcv[n * 2 + 1], wv + n * 4 + 2, acc);

            float r[G_];
            #pragma unroll
            for (int g = 0; g < G_; g++)
                asm("tanh.approx.f32 %0, %1;" : "=f"(r[g]) : "f"(acc[g]));

            if (!last) {
                __half2 p[G_ / 2];
                #pragma unroll
                for (int g = 0; g < G_ / 2; g++)
                    p[g] = __floats2half2_rn(r[2 * g], r[2 * g + 1]);
                *reinterpret_cast<uint4*>(nxt + (size_t)n * G_) =
                    *reinterpret_cast<const uint4*>(p);
            } else {
                #pragma unroll
                for (int g = 0; g < G_; g++)
                    out[(size_t)(b0 + g) * N_ + n] = r[g];
            }
        }
        __syncthreads();
    }
}

extern "C" void kernel_launch(void* const* d_in, const int* in_sizes, int n_in,
                              void* d_out, int out_size) {
    const float* x   = (const float*)d_in[0];
    const int*   src = (const int*)d_in[1];
    const float* w   = (const float*)d_in[2];
    float*       out = (float*)d_out;

    int octets = L_ * (N_ / 8);   // 4096
    prep_sched<<<(octets + 255) / 256, 256>>>(src, w);

    size_t smem = (size_t)2 * N_ * G_ * sizeof(__half);  // 128 KB
    cudaFuncSetAttribute(genome_kernel,
                         cudaFuncAttributeMaxDynamicSharedMemorySize, (int)smem);
    genome_kernel<<<NBLOCKS_, THREADS_, smem>>>(x, out);
}

// round 7
// speedup vs baseline: 2.5039x; 2.5039x over previous
#include <cuda_runtime.h>
#include <cuda_fp16.h>
#include <cstdint>

#define B_      1024
#define N_      4096
#define L_      8
#define K_      16
#define G_      8            // batch rows per block
#define THREADS_ 1024
#define NBLOCKS_ (B_ / G_)   // 128

// Scratch: schedule-permuted indices (uint16) and weights (fp32).
__device__ __align__(16) uint16_t g_src16[L_ * N_ * K_];   // 1 MB
__device__ __align__(16) float    g_wperm[L_ * N_ * K_];   // 2 MB

// Warp-cooperative per-octet gather scheduler.
// Main kernel: lanes 0-7 / 8-15 / ... of a warp are the LDS.128 crossbar
// phases; lane l of an octet processes n = octet_base + l. Terms commute, so
// each lane's 16 (s, w) pairs may be reordered freely. For each of 16 steps,
// each lane picks a pair whose bank-group (s & 7) is not yet claimed in the
// step (start lane rotates with the step). Near-Latin-square schedule.
// Producer layout: ONE THREAD PER LANE (8 threads/octet, 32K threads total),
// pairs held in registers via fully unrolled predicated selects; the only
// shared state (groupmask) is serialized across the octet with width-8
// shuffles. (R5's one-thread-per-octet version spilled 256 elements to local
// memory and cost ~330 us; this is the same schedule, parallel producer.)
__global__ void prep_sched(const int* __restrict__ src,
                           const float* __restrict__ w) {
    int gtid = blockIdx.x * blockDim.x + threadIdx.x;
    int octet = gtid >> 3;
    int lane8 = gtid & 7;
    if (octet >= L_ * (N_ / 8)) return;
    int l = octet / (N_ / 8);
    int n = (octet % (N_ / 8)) * 8 + lane8;

    const int*   sp = src + ((size_t)l * N_ + n) * K_;
    const float* wp = w   + ((size_t)l * N_ + n) * K_;
    uint16_t s[K_]; float wv[K_];
    #pragma unroll
    for (int k = 0; k < K_; k++) {
        s[k]  = (uint16_t)sp[k];
        wv[k] = wp[k];
    }

    unsigned rem = 0xFFFFu;
    uint16_t* so = g_src16 + ((size_t)l * N_ + n) * K_;
    float*    wo = g_wperm + ((size_t)l * N_ + n) * K_;

    #pragma unroll 1
    for (int step = 0; step < K_; step++) {
        unsigned groupmask = 0;
        uint16_t ps = 0; float pw = 0.0f;
        #pragma unroll 1
        for (int j = 0; j < 8; j++) {
            int a = (j + step) & 7;            // rotating start lane
            if (lane8 == a) {
                int pick = -1, fallback = -1;
                uint16_t fs = 0, qs = 0; float fw = 0.0f, qw = 0.0f;
                #pragma unroll
                for (int k = 0; k < K_; k++) {
                    bool avail = (rem >> k) & 1u;
                    bool gfree = !((groupmask >> (s[k] & 7)) & 1u);
                    if (avail && fallback < 0) { fallback = k; fs = s[k]; fw = wv[k]; }
                    if (avail && gfree && pick < 0) { pick = k; qs = s[k]; qw = wv[k]; }
                }
                if (pick < 0) { pick = fallback; qs = fs; qw = fw; }  // forced collision
                rem &= ~(1u << pick);
                groupmask |= 1u << (qs & 7);
                ps = qs; pw = qw;
            }
            // broadcast updated claim mask from the lane that just picked
            groupmask = __shfl_sync(0xFFFFFFFFu, groupmask, a, 8);
        }
        so[step] = ps;
        wo[step] = pw;
    }
}

// One gather index serves all G=8 batch rows: one LDS.128 of [s][0..7] fp16.
__device__ __forceinline__ void gather_fma(const __half* __restrict__ cur,
                                           uint32_t s, float wk, float* acc) {
    uint4 v = *reinterpret_cast<const uint4*>(cur + s * G_);
    float2 f;
    f = __half22float2(*reinterpret_cast<__half2*>(&v.x));
    acc[0] = fmaf(f.x, wk, acc[0]); acc[1] = fmaf(f.y, wk, acc[1]);
    f = __half22float2(*reinterpret_cast<__half2*>(&v.y));
    acc[2] = fmaf(f.x, wk, acc[2]); acc[3] = fmaf(f.y, wk, acc[3]);
    f = __half22float2(*reinterpret_cast<__half2*>(&v.z));
    acc[4] = fmaf(f.x, wk, acc[4]); acc[5] = fmaf(f.y, wk, acc[5]);
    f = __half22float2(*reinterpret_cast<__half2*>(&v.w));
    acc[6] = fmaf(f.x, wk, acc[6]); acc[7] = fmaf(f.y, wk, acc[7]);
}

__device__ __forceinline__ void half_k(const __half* __restrict__ cur,
                                       uint4 s, const float4* __restrict__ wv,
                                       float* acc) {
    float4 wa = wv[0];
    gather_fma(cur, s.x & 0xFFFFu, wa.x, acc);
    gather_fma(cur, s.x >> 16,     wa.y, acc);
    gather_fma(cur, s.y & 0xFFFFu, wa.z, acc);
    gather_fma(cur, s.y >> 16,     wa.w, acc);
    float4 wb = wv[1];
    gather_fma(cur, s.z & 0xFFFFu, wb.x, acc);
    gather_fma(cur, s.z >> 16,     wb.y, acc);
    gather_fma(cur, s.w & 0xFFFFu, wb.z, acc);
    gather_fma(cur, s.w >> 16,     wb.w, acc);
}

__global__ void __launch_bounds__(THREADS_, 1)
genome_kernel(const float* __restrict__ x, float* __restrict__ out) {
    extern __shared__ __half sm[];
    __half* bufA = sm;               // [N_][G_]
    __half* bufB = sm + N_ * G_;     // double buffer
    const int b0 = blockIdx.x * G_;

    for (int n = threadIdx.x; n < N_; n += THREADS_) {
        __half tmp[G_];
        #pragma unroll
        for (int g = 0; g < G_; g++)
            tmp[g] = __float2half_rn(x[(size_t)(b0 + g) * N_ + n]);
        *reinterpret_cast<uint4*>(bufA + (size_t)n * G_) =
            *reinterpret_cast<uint4*>(tmp);
    }
    __syncthreads();

    #pragma unroll 1
    for (int l = 0; l < L_; l++) {
        const __half* cur = (l & 1) ? bufB : bufA;
        __half*       nxt = (l & 1) ? bufA : bufB;
        const uint4*  srcv = reinterpret_cast<const uint4*>(g_src16) + (size_t)l * N_ * 2;
        const float4* wv   = reinterpret_cast<const float4*>(g_wperm) + (size_t)l * N_ * 4;
        const bool last = (l == L_ - 1);

        #pragma unroll 1
        for (int n = threadIdx.x; n < N_; n += THREADS_) {
            float acc[G_];
            #pragma unroll
            for (int g = 0; g < G_; g++) acc[g] = 0.0f;

            half_k(cur, srcv[n * 2 + 0], wv + n * 4 + 0, acc);
            half_k(cur, srcv[n * 2 + 1], wv + n * 4 + 2, acc);

            float r[G_];
            #pragma unroll
            for (int g = 0; g < G_; g++)
                asm("tanh.approx.f32 %0, %1;" : "=f"(r[g]) : "f"(acc[g]));

            if (!last) {
                __half2 p[G_ / 2];
                #pragma unroll
                for (int g = 0; g < G_ / 2; g++)
                    p[g] = __floats2half2_rn(r[2 * g], r[2 * g + 1]);
                *reinterpret_cast<uint4*>(nxt + (size_t)n * G_) =
                    *reinterpret_cast<const uint4*>(p);
            } else {
                #pragma unroll
                for (int g = 0; g < G_; g++)
                    out[(size_t)(b0 + g) * N_ + n] = r[g];
            }
        }
        __syncthreads();
    }
}

extern "C" void kernel_launch(void* const* d_in, const int* in_sizes, int n_in,
                              void* d_out, int out_size) {
    const float* x   = (const float*)d_in[0];
    const int*   src = (const int*)d_in[1];
    const float* w   = (const float*)d_in[2];
    float*       out = (float*)d_out;

    int total = L_ * N_;   // 8 threads per octet = L_*N_ threads total
    prep_sched<<<(total + 255) / 256, 256>>>(src, w);

    size_t smem = (size_t)2 * N_ * G_ * sizeof(__half);  // 128 KB
    cudaFuncSetAttribute(genome_kernel,
                         cudaFuncAttributeMaxDynamicSharedMemorySize, (int)smem);
    genome_kernel<<<NBLOCKS_, THREADS_, smem>>>(x, out);
}

// round 8
// speedup vs baseline: 2.8860x; 1.1526x over previous
#include <cuda_runtime.h>
#include <cuda_fp16.h>
#include <cstdint>

#define B_      1024
#define N_      4096
#define L_      8
#define K_      16
#define G_      8            // batch rows per block
#define THREADS_ 1024
#define NBLOCKS_ (B_ / G_)   // 128

// Scratch: schedule-permuted packed pairs: low 16 bits = index, high 16 = fp16 weight.
__device__ __align__(16) uint32_t g_pair[L_ * N_ * K_];    // 2 MB

// ---------------------------------------------------------------------------
// Parallel-matching per-octet gather scheduler.
// Main kernel: lanes 0-7 / 8-15 / ... of a warp are the LDS.128 crossbar
// phases; lane l of an octet processes n = octet_base + l. Terms commute, so
// each lane's 16 (s, w) pairs may be reordered freely. Per step, the 8 lanes
// must hit distinct bank-groups (s & 7) to avoid smem replays.
// Producer: one thread per lane. Pairs are counting-sorted by bank-group into
// a per-thread SHARED-memory bucket (dynamic indexing without local-mem
// spills); group counts/starts are packed in uint64 registers. Per step, all
// lanes pick CONCURRENTLY: each requests a group from (avail & ~claimed)
// (rotated first choice to decorrelate), __match_any_sync picks one winner
// per group, __reduce_or_sync merges the claimed mask, losers retry (4
// rounds), stragglers force-commit (= forced collision, same as serial
// greedy). ~2K instr/thread vs ~20K for the lane-serialized version (R7).
// ---------------------------------------------------------------------------
__global__ void prep_sched(const int* __restrict__ src,
                           const float* __restrict__ w) {
    __shared__ uint32_t buck[256 * K_];   // 16 KB: per-thread 16-pair bucket
    int gtid  = blockIdx.x * blockDim.x + threadIdx.x;
    int octet = gtid >> 3;
    int lane8 = gtid & 7;
    if (octet >= L_ * (N_ / 8)) return;   // whole octets only (grid is exact)
    int l = octet / (N_ / 8);
    int n = (octet % (N_ / 8)) * 8 + lane8;

    const int*   sp = src + ((size_t)l * N_ + n) * K_;
    const float* wp = w   + ((size_t)l * N_ + n) * K_;

    // Pack pairs + count per-group occupancy (8 groups x 8-bit counts).
    uint32_t pair[K_];
    uint64_t cnts = 0;
    #pragma unroll
    for (int k = 0; k < K_; k++) {
        uint32_t s16 = (uint32_t)sp[k] & 0xFFFFu;
        uint32_t w16 = (uint32_t)__half_as_ushort(__float2half_rn(wp[k]));
        pair[k] = s16 | (w16 << 16);
        cnts += 1ull << (8 * (s16 & 7));
    }
    // starts[g] = prefix sum of counts (packed 8x8 bits).
    uint64_t starts = 0;
    {
        uint32_t acc = 0;
        #pragma unroll
        for (int g = 0; g < 8; g++) {
            starts |= (uint64_t)acc << (8 * g);
            acc += (uint32_t)((cnts >> (8 * g)) & 0xFF);
        }
    }
    // Counting-sort into shared bucket.
    uint32_t base = threadIdx.x * K_;
    {
        uint64_t fill = 0;
        #pragma unroll
        for (int k = 0; k < K_; k++) {
            int g = pair[k] & 7;
            uint32_t idx = (uint32_t)((starts >> (8 * g)) & 0xFF)
                         + (uint32_t)((fill   >> (8 * g)) & 0xFF);
            fill += 1ull << (8 * g);
            buck[base + idx] = pair[k];
        }
    }
    // avail = groups with remaining pairs; remc = remaining counts.
    uint32_t avail = 0;
    #pragma unroll
    for (int g = 0; g < 8; g++)
        if ((cnts >> (8 * g)) & 0xFF) avail |= 1u << g;
    uint64_t remc = cnts;

    int lane_w   = threadIdx.x & 31;
    int oct_base = lane_w & ~7;
    unsigned octmask = 0xFFu << oct_base;

    uint32_t* out = g_pair + ((size_t)l * N_ + n) * K_;

    #pragma unroll 1
    for (int step = 0; step < K_; step++) {
        unsigned claimed = 0;
        int done = 0;
        int pick_g = 0;
        #pragma unroll 1
        for (int round = 0; round < 4; round++) {
            unsigned req = 8;                       // sentinel for done lanes
            if (!done) {
                unsigned m = avail & ~claimed;
                if (!m) m = avail;                  // forced-collision request
                int rot = (lane8 + step) & 7;       // decorrelate first choice
                unsigned mr = ((m | (m << 8)) >> rot) & 0xFFu;
                req = (unsigned)((__ffs(mr) - 1 + rot) & 7);
            }
            unsigned peers = __match_any_sync(octmask, req);
            unsigned p8 = (peers >> oct_base) & 0xFFu;
            int pri = (step + round) & 7;           // rotating winner priority
            unsigned pr = ((p8 | (p8 << 8)) >> pri) & 0xFFu;
            int win = (__ffs(pr) - 1 + pri) & 7;
            int iwin = (!done) && (win == lane8);
            unsigned contrib = iwin ? (1u << req) : 0u;
            claimed |= __reduce_or_sync(octmask, contrib);
            if (iwin) { pick_g = (int)req; done = 1; }
        }
        if (!done) pick_g = __ffs(avail) - 1;       // forced commit

        // Pop one pair from bucket pick_g.
        uint32_t c   = (uint32_t)((remc >> (8 * pick_g)) & 0xFF);
        uint32_t idx = (uint32_t)((starts >> (8 * pick_g)) & 0xFF) + c - 1;
        remc -= 1ull << (8 * pick_g);
        if (c == 1) avail &= ~(1u << pick_g);
        out[step] = buck[base + idx];
    }
}

// ---------------------------------------------------------------------------
// Main kernel. One gather index serves all G=8 batch rows: one LDS.128 of
// [s][0..7] fp16. Pairs arrive packed (idx | fp16 w << 16) in schedule order.
// ---------------------------------------------------------------------------
__device__ __forceinline__ void gather_fma(const __half* __restrict__ cur,
                                           uint32_t p, float* acc) {
    uint32_t s = p & 0xFFFFu;
    float wk = __half2float(__ushort_as_half((unsigned short)(p >> 16)));
    uint4 v = *reinterpret_cast<const uint4*>(cur + s * G_);
    float2 f;
    f = __half22float2(*reinterpret_cast<__half2*>(&v.x));
    acc[0] = fmaf(f.x, wk, acc[0]); acc[1] = fmaf(f.y, wk, acc[1]);
    f = __half22float2(*reinterpret_cast<__half2*>(&v.y));
    acc[2] = fmaf(f.x, wk, acc[2]); acc[3] = fmaf(f.y, wk, acc[3]);
    f = __half22float2(*reinterpret_cast<__half2*>(&v.z));
    acc[4] = fmaf(f.x, wk, acc[4]); acc[5] = fmaf(f.y, wk, acc[5]);
    f = __half22float2(*reinterpret_cast<__half2*>(&v.w));
    acc[6] = fmaf(f.x, wk, acc[6]); acc[7] = fmaf(f.y, wk, acc[7]);
}

__global__ void __launch_bounds__(THREADS_, 1)
genome_kernel(const float* __restrict__ x, float* __restrict__ out) {
    extern __shared__ __half sm[];
    __half* bufA = sm;               // [N_][G_]
    __half* bufB = sm + N_ * G_;     // double buffer
    const int b0 = blockIdx.x * G_;

    for (int n = threadIdx.x; n < N_; n += THREADS_) {
        __half tmp[G_];
        #pragma unroll
        for (int g = 0; g < G_; g++)
            tmp[g] = __float2half_rn(x[(size_t)(b0 + g) * N_ + n]);
        *reinterpret_cast<uint4*>(bufA + (size_t)n * G_) =
            *reinterpret_cast<uint4*>(tmp);
    }
    __syncthreads();

    #pragma unroll 1
    for (int l = 0; l < L_; l++) {
        const __half* cur = (l & 1) ? bufB : bufA;
        __half*       nxt = (l & 1) ? bufA : bufB;
        const uint4*  pv  = reinterpret_cast<const uint4*>(g_pair) + (size_t)l * N_ * 4;
        const bool last = (l == L_ - 1);

        #pragma unroll 1
        for (int n = threadIdx.x; n < N_; n += THREADS_) {
            float acc[G_];
            #pragma unroll
            for (int g = 0; g < G_; g++) acc[g] = 0.0f;

            #pragma unroll
            for (int q = 0; q < 4; q++) {           // 4 pairs per uint4
                uint4 p = pv[n * 4 + q];
                gather_fma(cur, p.x, acc);
                gather_fma(cur, p.y, acc);
                gather_fma(cur, p.z, acc);
                gather_fma(cur, p.w, acc);
            }

            float r[G_];
            #pragma unroll
            for (int g = 0; g < G_; g++)
                asm("tanh.approx.f32 %0, %1;" : "=f"(r[g]) : "f"(acc[g]));

            if (!last) {
                __half2 p[G_ / 2];
                #pragma unroll
                for (int g = 0; g < G_ / 2; g++)
                    p[g] = __floats2half2_rn(r[2 * g], r[2 * g + 1]);
                *reinterpret_cast<uint4*>(nxt + (size_t)n * G_) =
                    *reinterpret_cast<const uint4*>(p);
            } else {
                #pragma unroll
                for (int g = 0; g < G_; g++)
                    out[(size_t)(b0 + g) * N_ + n] = r[g];
            }
        }
        __syncthreads();
    }
}

extern "C" void kernel_launch(void* const* d_in, const int* in_sizes, int n_in,
                              void* d_out, int out_size) {
    const float* x   = (const float*)d_in[0];
    const int*   src = (const int*)d_in[1];
    const float* w   = (const float*)d_in[2];
    float*       out = (float*)d_out;

    int total = L_ * N_;   // 8 threads per octet
    prep_sched<<<(total + 255) / 256, 256>>>(src, w);

    size_t smem = (size_t)2 * N_ * G_ * sizeof(__half);  // 128 KB
    cudaFuncSetAttribute(genome_kernel,
                         cudaFuncAttributeMaxDynamicSharedMemorySize, (int)smem);
    genome_kernel<<<NBLOCKS_, THREADS_, smem>>>(x, out);
}

// round 9
// speedup vs baseline: 3.7165x; 1.2878x over previous
#include <cuda_runtime.h>
#include <cuda_fp16.h>
#include <cstdint>

#define B_      1024
#define N_      4096
#define L_      8
#define K_      16
#define G_      8            // batch rows per block
#define THREADS_ 1024
#define NBLOCKS_ (B_ / G_)   // 128

// Scratch: schedule-permuted packed pairs: low 16 = index, high 16 = fp16 weight.
__device__ __align__(16) uint32_t g_pair[L_ * N_ * K_];    // 2 MB

// ---------------------------------------------------------------------------
// Sync-free per-octet gather scheduler.
// Main kernel: lanes 0-7 / 8-15 / ... of a warp are the LDS.128 crossbar
// phases; lane l of an octet processes n = octet_base + l. Terms commute, so
// each lane's 16 (s, w) pairs may be reordered; per step the 8 lanes should
// hit distinct bank-groups (s & 7).
// The greedy schedule is a pure function of the 8 lanes' group-COUNT vectors.
// So: counting-sort pairs into a shared-mem bucket (dynamic indexing without
// spills), exchange count vectors once (8 shuffles), then EVERY lane
// redundantly computes the full 16-step x 8-lane assignment table in straight-
// line fully-unrolled ALU code (no sync ops, no divergence; R8's version
// chained 64 dependent MATCH/REDUX ops and cost ~43 us). Each lane keeps its
// own picks (4 bits/step) and pops pairs from its bucket.
// ---------------------------------------------------------------------------
__global__ void prep_sched(const int* __restrict__ src,
                           const float* __restrict__ w) {
    __shared__ uint32_t buck[256 * K_];   // 16 KB: per-thread 16-pair bucket
    int gtid  = blockIdx.x * blockDim.x + threadIdx.x;
    int octet = gtid >> 3;
    int lane8 = gtid & 7;
    if (octet >= L_ * (N_ / 8)) return;
    int l = octet / (N_ / 8);
    int n = (octet % (N_ / 8)) * 8 + lane8;

    const int*   sp = src + ((size_t)l * N_ + n) * K_;
    const float* wp = w   + ((size_t)l * N_ + n) * K_;

    // Pack pairs + per-group counts (8 groups x 8-bit lanes of a uint64).
    uint32_t pair[K_];
    uint64_t cnts = 0;
    #pragma unroll
    for (int k = 0; k < K_; k++) {
        uint32_t s16 = (uint32_t)sp[k] & 0xFFFFu;
        uint32_t w16 = (uint32_t)__half_as_ushort(__float2half_rn(wp[k]));
        pair[k] = s16 | (w16 << 16);
        cnts += 1ull << (8 * (s16 & 7));
    }
    // starts[g] = exclusive prefix sum of counts (packed 8x8 bits).
    uint64_t starts = 0;
    {
        uint32_t acc = 0;
        #pragma unroll
        for (int g = 0; g < 8; g++) {
            starts |= (uint64_t)acc << (8 * g);
            acc += (uint32_t)((cnts >> (8 * g)) & 0xFF);
        }
    }
    // Counting-sort into shared bucket.
    uint32_t base = threadIdx.x * K_;
    {
        uint64_t fill = 0;
        #pragma unroll
        for (int k = 0; k < K_; k++) {
            int g = pair[k] & 7;
            uint32_t idx = (uint32_t)((starts >> (8 * g)) & 0xFF)
                         + (uint32_t)((fill   >> (8 * g)) & 0xFF);
            fill += 1ull << (8 * g);
            buck[base + idx] = pair[k];
        }
    }

    // Exchange count vectors across the octet (one-time, 8 x 64-bit shuffle).
    uint64_t rem[8];
    #pragma unroll
    for (int j = 0; j < 8; j++)
        rem[j] = __shfl_sync(0xFFFFFFFFu, (unsigned long long)cnts, j, 8);

    // availAll: bit (8*j + g) set iff lane j still has pairs in group g.
    uint64_t availAll = 0;
    #pragma unroll
    for (int j = 0; j < 8; j++)
        #pragma unroll
        for (int g = 0; g < 8; g++)
            if ((rem[j] >> (8 * g)) & 0xFF) availAll |= 1ull << (8 * j + g);

    // Redundant local greedy: both loops fully unrolled so rem[] stays in
    // statically-indexed registers. Rotating start lane + rotating first
    // choice; fallback = forced collision.
    uint64_t mypicks = 0;   // 4 bits per step
    #pragma unroll
    for (int step = 0; step < K_; step++) {
        uint32_t claimed = 0;
        #pragma unroll
        for (int li = 0; li < 8; li++) {
            const int a = (li + step) & 7;              // compile-time
            uint32_t av = (uint32_t)(availAll >> (8 * a)) & 0xFFu;
            uint32_t m = av & ~claimed;
            if (!m) m = av;                             // forced collision
            const int rot = (a + step) & 7;             // compile-time
            uint32_t mr = ((m | (m << 8)) >> rot) & 0xFFu;
            int g = (__ffs(mr) - 1 + rot) & 7;
            claimed |= 1u << g;
            rem[a] -= 1ull << (8 * g);
            if (!((rem[a] >> (8 * g)) & 0xFF))
                availAll &= ~(1ull << (8 * a + g));
            if (lane8 == a)
                mypicks |= (uint64_t)g << (4 * step);
        }
    }

    // Pop pairs from the bucket in schedule order and emit.
    uint32_t* out = g_pair + ((size_t)l * N_ + n) * K_;
    uint64_t remc = cnts;
    #pragma unroll
    for (int step = 0; step < K_; step++) {
        int g = (int)((mypicks >> (4 * step)) & 15);
        uint32_t c   = (uint32_t)((remc >> (8 * g)) & 0xFF);
        uint32_t idx = (uint32_t)((starts >> (8 * g)) & 0xFF) + c - 1;
        remc -= 1ull << (8 * g);
        out[step] = buck[base + idx];
    }
}

// ---------------------------------------------------------------------------
// Main kernel. One gather index serves all G=8 batch rows: one LDS.128 of
// [s][0..7] fp16. Pairs arrive packed (idx | fp16 w << 16) in schedule order.
// ---------------------------------------------------------------------------
__device__ __forceinline__ void gather_fma(const __half* __restrict__ cur,
                                           uint32_t p, float* acc) {
    uint32_t s = p & 0xFFFFu;
    float wk = __half2float(__ushort_as_half((unsigned short)(p >> 16)));
    uint4 v = *reinterpret_cast<const uint4*>(cur + s * G_);
    float2 f;
    f = __half22float2(*reinterpret_cast<__half2*>(&v.x));
    acc[0] = fmaf(f.x, wk, acc[0]); acc[1] = fmaf(f.y, wk, acc[1]);
    f = __half22float2(*reinterpret_cast<__half2*>(&v.y));
    acc[2] = fmaf(f.x, wk, acc[2]); acc[3] = fmaf(f.y, wk, acc[3]);
    f = __half22float2(*reinterpret_cast<__half2*>(&v.z));
    acc[4] = fmaf(f.x, wk, acc[4]); acc[5] = fmaf(f.y, wk, acc[5]);
    f = __half22float2(*reinterpret_cast<__half2*>(&v.w));
    acc[6] = fmaf(f.x, wk, acc[6]); acc[7] = fmaf(f.y, wk, acc[7]);
}

__global__ void __launch_bounds__(THREADS_, 1)
genome_kernel(const float* __restrict__ x, float* __restrict__ out) {
    extern __shared__ __half sm[];
    __half* bufA = sm;               // [N_][G_]
    __half* bufB = sm + N_ * G_;     // double buffer
    const int b0 = blockIdx.x * G_;

    for (int n = threadIdx.x; n < N_; n += THREADS_) {
        __half tmp[G_];
        #pragma unroll
        for (int g = 0; g < G_; g++)
            tmp[g] = __float2half_rn(x[(size_t)(b0 + g) * N_ + n]);
        *reinterpret_cast<uint4*>(bufA + (size_t)n * G_) =
            *reinterpret_cast<uint4*>(tmp);
    }
    __syncthreads();

    #pragma unroll 1
    for (int l = 0; l < L_; l++) {
        const __half* cur = (l & 1) ? bufB : bufA;
        __half*       nxt = (l & 1) ? bufA : bufB;
        const uint4*  pv  = reinterpret_cast<const uint4*>(g_pair) + (size_t)l * N_ * 4;
        const bool last = (l == L_ - 1);

        #pragma unroll 1
        for (int n = threadIdx.x; n < N_; n += THREADS_) {
            float acc[G_];
            #pragma unroll
            for (int g = 0; g < G_; g++) acc[g] = 0.0f;

            #pragma unroll
            for (int q = 0; q < 4; q++) {           // 4 pairs per uint4
                uint4 p = pv[n * 4 + q];
                gather_fma(cur, p.x, acc);
                gather_fma(cur, p.y, acc);
                gather_fma(cur, p.z, acc);
                gather_fma(cur, p.w, acc);
            }

            float r[G_];
            #pragma unroll
            for (int g = 0; g < G_; g++)
                asm("tanh.approx.f32 %0, %1;" : "=f"(r[g]) : "f"(acc[g]));

            if (!last) {
                __half2 p[G_ / 2];
                #pragma unroll
                for (int g = 0; g < G_ / 2; g++)
                    p[g] = __floats2half2_rn(r[2 * g], r[2 * g + 1]);
                *reinterpret_cast<uint4*>(nxt + (size_t)n * G_) =
                    *reinterpret_cast<const uint4*>(p);
            } else {
                #pragma unroll
                for (int g = 0; g < G_; g++)
                    out[(size_t)(b0 + g) * N_ + n] = r[g];
            }
        }
        __syncthreads();
    }
}

extern "C" void kernel_launch(void* const* d_in, const int* in_sizes, int n_in,
                              void* d_out, int out_size) {
    const float* x   = (const float*)d_in[0];
    const int*   src = (const int*)d_in[1];
    const float* w   = (const float*)d_in[2];
    float*       out = (float*)d_out;

    int total = L_ * N_;   // 8 threads per octet
    prep_sched<<<(total + 255) / 256, 256>>>(src, w);

    size_t smem = (size_t)2 * N_ * G_ * sizeof(__half);  // 128 KB
    cudaFuncSetAttribute(genome_kernel,
                         cudaFuncAttributeMaxDynamicSharedMemorySize, (int)smem);
    genome_kernel<<<NBLOCKS_, THREADS_, smem>>>(x, out);
}

// round 10
// speedup vs baseline: 3.7295x; 1.0035x over previous
#include <cuda_runtime.h>
#include <cuda_fp16.h>
#include <cstdint>

#define B_      1024
#define N_      4096
#define L_      8
#define K_      16
#define G_      8            // batch rows per block
#define THREADS_ 512         // 8 n-iters; frees reg cap to 128/thread
#define NBLOCKS_ (B_ / G_)   // 128

// Scratch: schedule-permuted packed pairs: low 16 = index, high 16 = fp16 weight.
__device__ __align__(16) uint32_t g_pair[L_ * N_ * K_];    // 2 MB

// ---------------------------------------------------------------------------
// Sync-free per-octet gather scheduler (unchanged from R9, which measured
// ~7 us kernel + launch overhead). Lanes 0-7/8-15/... of a warp are the
// LDS.128 crossbar phases; terms commute; per step the 8 lanes should hit
// distinct bank-groups (s & 7). Greedy is a pure function of the octet's
// group-count vectors: counting-sort pairs into a shared bucket, exchange
// count vectors once, every lane redundantly computes the 16x8 assignment
// table in fully-unrolled straight-line ALU code, pops pairs in order.
// ---------------------------------------------------------------------------
__global__ void prep_sched(const int* __restrict__ src,
                           const float* __restrict__ w) {
    __shared__ uint32_t buck[128 * K_];   // 8 KB: per-thread 16-pair bucket
    int gtid  = blockIdx.x * blockDim.x + threadIdx.x;
    int octet = gtid >> 3;
    int lane8 = gtid & 7;
    if (octet >= L_ * (N_ / 8)) return;
    int l = octet / (N_ / 8);
    int n = (octet % (N_ / 8)) * 8 + lane8;

    const int*   sp = src + ((size_t)l * N_ + n) * K_;
    const float* wp = w   + ((size_t)l * N_ + n) * K_;

    uint32_t pair[K_];
    uint64_t cnts = 0;
    #pragma unroll
    for (int k = 0; k < K_; k++) {
        uint32_t s16 = (uint32_t)sp[k] & 0xFFFFu;
        uint32_t w16 = (uint32_t)__half_as_ushort(__float2half_rn(wp[k]));
        pair[k] = s16 | (w16 << 16);
        cnts += 1ull << (8 * (s16 & 7));
    }
    uint64_t starts = 0;
    {
        uint32_t acc = 0;
        #pragma unroll
        for (int g = 0; g < 8; g++) {
            starts |= (uint64_t)acc << (8 * g);
            acc += (uint32_t)((cnts >> (8 * g)) & 0xFF);
        }
    }
    uint32_t base = threadIdx.x * K_;
    {
        uint64_t fill = 0;
        #pragma unroll
        for (int k = 0; k < K_; k++) {
            int g = pair[k] & 7;
            uint32_t idx = (uint32_t)((starts >> (8 * g)) & 0xFF)
                         + (uint32_t)((fill   >> (8 * g)) & 0xFF);
            fill += 1ull << (8 * g);
            buck[base + idx] = pair[k];
        }
    }

    uint64_t rem[8];
    #pragma unroll
    for (int j = 0; j < 8; j++)
        rem[j] = __shfl_sync(0xFFFFFFFFu, (unsigned long long)cnts, j, 8);

    uint64_t availAll = 0;
    #pragma unroll
    for (int j = 0; j < 8; j++)
        #pragma unroll
        for (int g = 0; g < 8; g++)
            if ((rem[j] >> (8 * g)) & 0xFF) availAll |= 1ull << (8 * j + g);

    uint64_t mypicks = 0;   // 4 bits per step
    #pragma unroll
    for (int step = 0; step < K_; step++) {
        uint32_t claimed = 0;
        #pragma unroll
        for (int li = 0; li < 8; li++) {
            const int a = (li + step) & 7;              // compile-time
            uint32_t av = (uint32_t)(availAll >> (8 * a)) & 0xFFu;
            uint32_t m = av & ~claimed;
            if (!m) m = av;                             // forced collision
            const int rot = (a + step) & 7;             // compile-time
            uint32_t mr = ((m | (m << 8)) >> rot) & 0xFFu;
            int g = (__ffs(mr) - 1 + rot) & 7;
            claimed |= 1u << g;
            rem[a] -= 1ull << (8 * g);
            if (!((rem[a] >> (8 * g)) & 0xFF))
                availAll &= ~(1ull << (8 * a + g));
            if (lane8 == a)
                mypicks |= (uint64_t)g << (4 * step);
        }
    }

    uint32_t* out = g_pair + ((size_t)l * N_ + n) * K_;
    uint64_t remc = cnts;
    #pragma unroll
    for (int step = 0; step < K_; step++) {
        int g = (int)((mypicks >> (4 * step)) & 15);
        uint32_t c   = (uint32_t)((remc >> (8 * g)) & 0xFF);
        uint32_t idx = (uint32_t)((starts >> (8 * g)) & 0xFF) + c - 1;
        remc -= 1ull << (8 * g);
        out[step] = buck[base + idx];
    }
}

// ---------------------------------------------------------------------------
// Main kernel. One gather index serves all G=8 batch rows: one LDS.128 of
// [s][0..7] fp16. Pairs arrive packed (idx | fp16 w << 16) in schedule order.
// 512 threads -> 128-reg budget: ptxas can keep many gather results in
// flight; next iteration's pair vectors are explicitly prefetched.
// ---------------------------------------------------------------------------
__device__ __forceinline__ void gather_fma(const __half* __restrict__ cur,
                                           uint32_t p, float* acc) {
    uint32_t s = p & 0xFFFFu;
    float wk = __half2float(__ushort_as_half((unsigned short)(p >> 16)));
    uint4 v = *reinterpret_cast<const uint4*>(cur + s * G_);
    float2 f;
    f = __half22float2(*reinterpret_cast<__half2*>(&v.x));
    acc[0] = fmaf(f.x, wk, acc[0]); acc[1] = fmaf(f.y, wk, acc[1]);
    f = __half22float2(*reinterpret_cast<__half2*>(&v.y));
    acc[2] = fmaf(f.x, wk, acc[2]); acc[3] = fmaf(f.y, wk, acc[3]);
    f = __half22float2(*reinterpret_cast<__half2*>(&v.z));
    acc[4] = fmaf(f.x, wk, acc[4]); acc[5] = fmaf(f.y, wk, acc[5]);
    f = __half22float2(*reinterpret_cast<__half2*>(&v.w));
    acc[6] = fmaf(f.x, wk, acc[6]); acc[7] = fmaf(f.y, wk, acc[7]);
}

__global__ void __launch_bounds__(THREADS_, 1)
genome_kernel(const float* __restrict__ x, float* __restrict__ out) {
    extern __shared__ __half sm[];
    __half* bufA = sm;               // [N_][G_]
    __half* bufB = sm + N_ * G_;     // double buffer
    const int b0 = blockIdx.x * G_;

    for (int n = threadIdx.x; n < N_; n += THREADS_) {
        __half tmp[G_];
        #pragma unroll
        for (int g = 0; g < G_; g++)
            tmp[g] = __float2half_rn(x[(size_t)(b0 + g) * N_ + n]);
        *reinterpret_cast<uint4*>(bufA + (size_t)n * G_) =
            *reinterpret_cast<uint4*>(tmp);
    }
    __syncthreads();

    #pragma unroll 1
    for (int l = 0; l < L_; l++) {
        const __half* cur = (l & 1) ? bufB : bufA;
        __half*       nxt = (l & 1) ? bufA : bufB;
        const uint4*  pv  = reinterpret_cast<const uint4*>(g_pair) + (size_t)l * N_ * 4;
        const bool last = (l == L_ - 1);

        // Software-pipelined over 8 n-iterations: prefetch next iter's pairs.
        int n = threadIdx.x;
        uint4 pa = pv[n * 4 + 0];
        uint4 pb = pv[n * 4 + 1];
        uint4 pc = pv[n * 4 + 2];
        uint4 pd = pv[n * 4 + 3];

        #pragma unroll 1
        for (int it = 0; it < N_ / THREADS_; it++) {
            uint4 qa = pa, qb = pb, qc = pc, qd = pd;
            int ncur = n;
            int nn = n + THREADS_;
            if (it < N_ / THREADS_ - 1) {
                pa = pv[nn * 4 + 0];
                pb = pv[nn * 4 + 1];
                pc = pv[nn * 4 + 2];
                pd = pv[nn * 4 + 3];
            }
            n = nn;

            float acc[G_];
            #pragma unroll
            for (int g = 0; g < G_; g++) acc[g] = 0.0f;

            gather_fma(cur, qa.x, acc); gather_fma(cur, qa.y, acc);
            gather_fma(cur, qa.z, acc); gather_fma(cur, qa.w, acc);
            gather_fma(cur, qb.x, acc); gather_fma(cur, qb.y, acc);
            gather_fma(cur, qb.z, acc); gather_fma(cur, qb.w, acc);
            gather_fma(cur, qc.x, acc); gather_fma(cur, qc.y, acc);
            gather_fma(cur, qc.z, acc); gather_fma(cur, qc.w, acc);
            gather_fma(cur, qd.x, acc); gather_fma(cur, qd.y, acc);
            gather_fma(cur, qd.z, acc); gather_fma(cur, qd.w, acc);

            float r[G_];
            #pragma unroll
            for (int g = 0; g < G_; g++)
                asm("tanh.approx.f32 %0, %1;" : "=f"(r[g]) : "f"(acc[g]));

            if (!last) {
                __half2 p[G_ / 2];
                #pragma unroll
                for (int g = 0; g < G_ / 2; g++)
                    p[g] = __floats2half2_rn(r[2 * g], r[2 * g + 1]);
                *reinterpret_cast<uint4*>(nxt + (size_t)ncur * G_) =
                    *reinterpret_cast<const uint4*>(p);
            } else {
                #pragma unroll
                for (int g = 0; g < G_; g++)
                    out[(size_t)(b0 + g) * N_ + ncur] = r[g];
            }
        }
        __syncthreads();
    }
}

extern "C" void kernel_launch(void* const* d_in, const int* in_sizes, int n_in,
                              void* d_out, int out_size) {
    const float* x   = (const float*)d_in[0];
    const int*   src = (const int*)d_in[1];
    const float* w   = (const float*)d_in[2];
    float*       out = (float*)d_out;

    int total = L_ * N_;   // 8 threads per octet
    prep_sched<<<(total + 127) / 128, 128>>>(src, w);

    size_t smem = (size_t)2 * N_ * G_ * sizeof(__half);  // 128 KB
    cudaFuncSetAttribute(genome_kernel,
                         cudaFuncAttributeMaxDynamicSharedMemorySize, (int)smem);
    genome_kernel<<<NBLOCKS_, THREADS_, smem>>>(x, out);
}